// round 2
// baseline (speedup 1.0000x reference)
#include <cuda_runtime.h>

// Problem constants
#define BQ    4
#define CCH   2
#define SLEN  4096
#define KW    64
#define NKF   32
#define OUTC  512
#define TDIM  72        // padded t-range; valid t = 0..64
#define KSPLIT 16
#define QCHUNK 256      // K (=q) elements per split-K block
#define XSLEN  584      // 2*255 + 72 + 9 slack, 8B aligned
#define WSROW  65       // ws2 row stride in float2 (odd -> spread banks)

// Scratch (device globals: no allocations allowed)
__device__ float g_Tpart[KSPLIT * BQ * OUTC * TDIM];   // 9.4 MB partials

// ---- packed f32x2 helpers (sm_100+; 2x FFMA lane throughput) ----
__device__ __forceinline__ void ffma2(unsigned long long& d, unsigned long long a, unsigned long long b) {
    asm("fma.rn.f32x2 %0, %1, %2, %0;" : "+l"(d) : "l"(a), "l"(b));
}
__device__ __forceinline__ float2 unpack2(unsigned long long v) {
    float2 r;
    asm("mov.b64 {%0, %1}, %2;" : "=f"(r.x), "=f"(r.y) : "l"(v));
    return r;
}

// ============================================================================
// Kernel A: partial strided-correlation GEMM
//   Tpart[kc][b][o][t] = sum over this block's q-chunk of
//       conv_w[o, c*2048+q] * xpad[b, c, 2q+t]
// Block: 288 threads = 32 o-rows x 9 t-cols. Thread: 2 o's x 8 t's
// (4 f32x2 accumulator pairs per o). x window rolls one pair per q step.
// conv_w is staged into smem as DUPLICATED float2 pairs so the inner loop
// is pure LDS.64 + FFMA2 (no packing ALU work).
// Grid: (8 o-tiles, 4 batch, 16 k-chunks) = 512 blocks x 9 warps.
// ============================================================================
__global__ __launch_bounds__(288, 4)
void gemm_partial_kernel(const float* __restrict__ x,
                         const float* __restrict__ conv_w) {
    __shared__ __align__(16) float xs[XSLEN];
    __shared__ __align__(16) float2 ws2[64 * WSROW];   // duplicated weights

    const int otile = blockIdx.x;   // 0..7  -> 64 o's each
    const int b     = blockIdx.y;   // 0..3
    const int kc    = blockIdx.z;   // 0..15 -> 256 q each

    const int tid = threadIdx.x;
    const int k0  = kc * QCHUNK;
    const int ci  = k0 >> 11;       // channel for this chunk
    const int qq0 = k0 & 2047;      // q offset within channel
    const int obase = otile * 64;

    // Stage x slice: xs[j] = xpad[b, ci, 2*qq0 + j]
    const float* xrow = x + (b * CCH + ci) * SLEN;
    for (int i = tid; i < XSLEN; i += 288) {
        int g = 2 * qq0 + i;
        xs[i] = (g < SLEN) ? xrow[g] : 0.0f;
    }

    const int row  = tid / 9;        // 0..31
    const int col  = tid - row * 9;  // 0..8
    const int t0   = col * 8;        // 0,8,...,64
    const int row2 = row * 2;

    __syncthreads();

    // rolling x window: 4 packed pairs covering xs[t0 .. t0+7] at q=0
    unsigned long long P0 = *(const unsigned long long*)&xs[t0 + 0];
    unsigned long long P1 = *(const unsigned long long*)&xs[t0 + 2];
    unsigned long long P2 = *(const unsigned long long*)&xs[t0 + 4];
    unsigned long long P3 = *(const unsigned long long*)&xs[t0 + 6];

    unsigned long long acc[2][4];
    #pragma unroll
    for (int j = 0; j < 2; j++)
        #pragma unroll
        for (int p = 0; p < 4; p++)
            acc[j][p] = 0ull;  // packed (0.0f, 0.0f)

    const float* wbase = conv_w + (size_t)obase * 4096 + k0;

    for (int kk0 = 0; kk0 < QCHUNK; kk0 += 64) {
        __syncthreads();  // previous compute done reading ws2
        #pragma unroll
        for (int i = tid; i < 64 * 64; i += 288) {
            int ol = i >> 6, kx = i & 63;
            float w = __ldg(&wbase[(size_t)ol * 4096 + (kk0 + kx)]);
            ws2[ol * WSROW + kx] = make_float2(w, w);
        }
        __syncthreads();

        #pragma unroll 16
        for (int kk = 0; kk < 64; kk++) {
            const int ql = kk0 + kk;
            unsigned long long wp0 = *(const unsigned long long*)&ws2[(row2 + 0) * WSROW + kk];
            unsigned long long wp1 = *(const unsigned long long*)&ws2[(row2 + 1) * WSROW + kk];

            ffma2(acc[0][0], wp0, P0); ffma2(acc[0][1], wp0, P1);
            ffma2(acc[0][2], wp0, P2); ffma2(acc[0][3], wp0, P3);
            ffma2(acc[1][0], wp1, P0); ffma2(acc[1][1], wp1, P1);
            ffma2(acc[1][2], wp1, P2); ffma2(acc[1][3], wp1, P3);

            // shift window by 2 (one pair): xs[2*(ql+1)+t0+6 .. +7]
            unsigned long long Pn = *(const unsigned long long*)&xs[2 * ql + t0 + 8];
            P0 = P1; P1 = P2; P2 = P3; P3 = Pn;
        }
    }

    // write partials: Tpart[kc][b][o][t]
    float* tp = g_Tpart + ((size_t)(kc * BQ + b) * OUTC) * TDIM;
    #pragma unroll
    for (int j = 0; j < 2; j++) {
        float* dst = tp + (size_t)(obase + row2 + j) * TDIM + t0;
        #pragma unroll
        for (int p = 0; p < 4; p++) {
            float2 v = unpack2(acc[j][p]);
            dst[2 * p]     = v.x;
            dst[2 * p + 1] = v.y;
        }
    }
}

// ============================================================================
// Kernel B: fused split-K reduce + epilogue
//   T[b,o,t]   = sum_kc Tpart[kc][b][o][t]
//   out[b,o, p*2048 + m*32 + l] = relu( stft_w[l,m] * T[b,o,p+m] + conv_b[o] )
// Block per (b,o): 256 threads, 4 float4 stores each (coalesced STG.128).
// ============================================================================
__global__ __launch_bounds__(256)
void epilogue_kernel(const float* __restrict__ stft_w,
                     const float* __restrict__ conv_b,
                     float* __restrict__ out) {
    __shared__ __align__(16) float swT[2048];   // transposed: swT[m*32 + l]
    __shared__ float Ts[TDIM];

    const int bo  = blockIdx.x;       // b*512 + o
    const int b   = bo >> 9;
    const int o   = bo & 511;
    const int tid = threadIdx.x;

    for (int i = tid; i < 2048; i += 256) {
        int l = i >> 6, m = i & 63;
        swT[m * 32 + l] = stft_w[i];
    }
    if (tid < TDIM) {
        float s = 0.0f;
        #pragma unroll
        for (int ks = 0; ks < KSPLIT; ks++)
            s += g_Tpart[((size_t)(ks * BQ + b) * OUTC + o) * TDIM + tid];
        Ts[tid] = s;
    }
    const float bias = conv_b[o];
    __syncthreads();

    float4* out4 = (float4*)(out + (size_t)bo * 4096);
    #pragma unroll
    for (int it = 0; it < 4; it++) {
        int q  = tid + it * 256;      // quad index; s' = 4*q
        int sp = q * 4;
        int p  = sp >> 11;
        int m  = (sp >> 5) & 63;
        int l0 = sp & 31;             // multiple of 4
        float tv = Ts[p + m];
        float4 sw = *(const float4*)&swT[m * 32 + l0];
        float4 r;
        r.x = fmaxf(fmaf(sw.x, tv, bias), 0.0f);
        r.y = fmaxf(fmaf(sw.y, tv, bias), 0.0f);
        r.z = fmaxf(fmaf(sw.z, tv, bias), 0.0f);
        r.w = fmaxf(fmaf(sw.w, tv, bias), 0.0f);
        out4[q] = r;
    }
}

// ============================================================================
extern "C" void kernel_launch(void* const* d_in, const int* in_sizes, int n_in,
                              void* d_out, int out_size) {
    const float* x      = nullptr;
    const float* stft_w = nullptr;
    const float* conv_w = nullptr;
    const float* conv_b = nullptr;
    for (int i = 0; i < n_in; i++) {
        switch (in_sizes[i]) {
            case BQ * CCH * SLEN:  x      = (const float*)d_in[i]; break;  // 32768
            case NKF * KW:         stft_w = (const float*)d_in[i]; break;  // 2048
            case OUTC * 4096:      conv_w = (const float*)d_in[i]; break;  // 2097152
            case OUTC:             conv_b = (const float*)d_in[i]; break;  // 512
        }
    }

    gemm_partial_kernel<<<dim3(8, BQ, KSPLIT), 288>>>(x, conv_w);
    epilogue_kernel<<<BQ * OUTC, 256>>>(stft_w, conv_b, (float*)d_out);
}

// round 3
// speedup vs baseline: 1.2240x; 1.2240x over previous
#include <cuda_runtime.h>

// Problem constants
#define BQ    4
#define CCH   2
#define SLEN  4096
#define KW    64
#define NKF   32
#define OUTC  512
#define TDIM  72        // padded t-range; valid t = 0..64
#define KSPLIT 16
#define QCHUNK 256      // K (=q) elements per split-K block
#define XSLEN  584      // 2*255 + 72 + slack
#define SWROW 36        // padded swT row (floats): 4-aligned, bank-spread

// Scratch (device globals: no allocations allowed)
__device__ float g_Tpart[KSPLIT * BQ * OUTC * TDIM];   // 9.4 MB partials
__device__ float g_Tred[BQ * OUTC * TDIM];

// ---- packed f32x2 helpers (sm_100+; 2x FFMA lane throughput) ----
__device__ __forceinline__ unsigned long long pack2(float a, float b) {
    unsigned long long r;
    asm("mov.b64 %0, {%1, %2};" : "=l"(r) : "f"(a), "f"(b));
    return r;
}
__device__ __forceinline__ void ffma2(unsigned long long& d, unsigned long long a, unsigned long long b) {
    asm("fma.rn.f32x2 %0, %1, %2, %0;" : "+l"(d) : "l"(a), "l"(b));
}
__device__ __forceinline__ float2 unpack2(unsigned long long v) {
    float2 r;
    asm("mov.b64 {%0, %1}, %2;" : "=f"(r.x), "=f"(r.y) : "l"(v));
    return r;
}

// ============================================================================
// Kernel A: partial strided-correlation GEMM
//   Tpart[kc][b][o][t] = sum over this block's q-chunk of
//       conv_w[o, c*2048+q] * xpad[b, c, 2q+t]
// Block: 288 threads (9 full warps) = 32 o-rows x 9 t-cols. Thread: 2o x 8t.
// Weights read straight from gmem (L2-resident; 9 threads/warp share each
// address -> broadcast wavefront) with float4 register double-buffering.
// x window rolls in registers from a tiny smem slice. NO syncs in main loop.
// ============================================================================
__global__ __launch_bounds__(288, 4)
void gemm_partial_kernel(const float* __restrict__ x,
                         const float* __restrict__ conv_w) {
    __shared__ __align__(16) float xs[XSLEN];

    const int otile = blockIdx.x;   // 0..7  -> 64 o's each
    const int b     = blockIdx.y;   // 0..3
    const int kc    = blockIdx.z;   // 0..15 -> 256 q each

    const int tid = threadIdx.x;
    const int k0  = kc * QCHUNK;
    const int ci  = k0 >> 11;       // channel for this chunk
    const int qq0 = k0 & 2047;      // q offset within channel
    const int obase = otile * 64;

    // Stage x slice: xs[j] = xpad[b, ci, 2*qq0 + j]
    const float* xrow = x + (b * CCH + ci) * SLEN;
    for (int i = tid; i < XSLEN; i += 288) {
        int g = 2 * qq0 + i;
        xs[i] = (g < SLEN) ? xrow[g] : 0.0f;
    }

    const int row  = tid / 9;        // 0..31
    const int col  = tid - row * 9;  // 0..8
    const int t0   = col * 8;        // 0,8,...,64
    const int row2 = row * 2;

    __syncthreads();

    // rolling x window: 4 packed pairs covering xs[t0 .. t0+7] at q=0
    unsigned long long P0 = *(const unsigned long long*)&xs[t0 + 0];
    unsigned long long P1 = *(const unsigned long long*)&xs[t0 + 2];
    unsigned long long P2 = *(const unsigned long long*)&xs[t0 + 4];
    unsigned long long P3 = *(const unsigned long long*)&xs[t0 + 6];

    unsigned long long acc[2][4];
    #pragma unroll
    for (int j = 0; j < 2; j++)
        #pragma unroll
        for (int p = 0; p < 4; p++)
            acc[j][p] = 0ull;

    const float* w0 = conv_w + (size_t)(obase + row2) * 4096 + k0;
    const float* w1 = w0 + 4096;

    // register double-buffer: 4 k-steps of weights for both o rows
    float4 ca = __ldg((const float4*)(w0));
    float4 cb = __ldg((const float4*)(w1));

    for (int kk0 = 0; kk0 < QCHUNK; kk0 += 4) {
        const int nxt = (kk0 + 4 < QCHUNK) ? (kk0 + 4) : 0;  // safe addr
        float4 na = __ldg((const float4*)(w0 + nxt));
        float4 nb = __ldg((const float4*)(w1 + nxt));

        float wa[4] = {ca.x, ca.y, ca.z, ca.w};
        float wb[4] = {cb.x, cb.y, cb.z, cb.w};

        #pragma unroll
        for (int j = 0; j < 4; j++) {
            unsigned long long wp0 = pack2(wa[j], wa[j]);
            unsigned long long wp1 = pack2(wb[j], wb[j]);

            ffma2(acc[0][0], wp0, P0); ffma2(acc[0][1], wp0, P1);
            ffma2(acc[0][2], wp0, P2); ffma2(acc[0][3], wp0, P3);
            ffma2(acc[1][0], wp1, P0); ffma2(acc[1][1], wp1, P1);
            ffma2(acc[1][2], wp1, P2); ffma2(acc[1][3], wp1, P3);

            // shift window by 2 (one pair): xs[2*(ql+1)+t0+6 .. +7]
            unsigned long long Pn = *(const unsigned long long*)&xs[2 * (kk0 + j) + t0 + 8];
            P0 = P1; P1 = P2; P2 = P3; P3 = Pn;
        }

        ca = na; cb = nb;
    }

    // write partials: Tpart[kc][b][o][t]
    float* tp = g_Tpart + ((size_t)(kc * BQ + b) * OUTC) * TDIM;
    #pragma unroll
    for (int j = 0; j < 2; j++) {
        float* dst = tp + (size_t)(obase + row2 + j) * TDIM + t0;
        #pragma unroll
        for (int p = 0; p < 4; p++) {
            float2 v = unpack2(acc[j][p]);
            dst[2 * p]     = v.x;
            dst[2 * p + 1] = v.y;
        }
    }
}

// ============================================================================
// Kernel B: split-K reduction (fully coalesced)
// ============================================================================
__global__ __launch_bounds__(256)
void reduce_kernel() {
    int i = blockIdx.x * 256 + threadIdx.x;   // grid sized exactly
    float s = 0.0f;
    #pragma unroll
    for (int ks = 0; ks < KSPLIT; ks++)
        s += g_Tpart[(size_t)ks * (BQ * OUTC * TDIM) + i];
    g_Tred[i] = s;
}

// ============================================================================
// Kernel C: epilogue (4 bo per block)
//   out[b,o, p*2048 + m*32 + l] = relu( stft_w[l,m] * T[b,o,p+m] + conv_b[o] )
// Block handles 4 consecutive bo; swT staged ONCE per 4 outputs.
// ============================================================================
#define BO_PER_BLK 4
__global__ __launch_bounds__(256)
void epilogue_kernel(const float* __restrict__ stft_w,
                     const float* __restrict__ conv_b,
                     float* __restrict__ out) {
    __shared__ __align__(16) float swT[64 * SWROW];   // transposed: swT[m*36 + l]
    __shared__ float Ts[BO_PER_BLK * TDIM];           // 288
    __shared__ float biasS[BO_PER_BLK];

    const int bo0 = blockIdx.x * BO_PER_BLK;
    const int tid = threadIdx.x;

    // stage stft_w transposed: swT[m*36 + l] = stft_w[l*64 + m]
    for (int i = tid; i < 2048; i += 256) {
        int l = i >> 6, m = i & 63;
        swT[m * SWROW + l] = stft_w[i];
    }
    // stage T for 4 bo (coalesced: g_Tred is [bo][72] contiguous)
    for (int i = tid; i < BO_PER_BLK * TDIM; i += 256)
        Ts[i] = g_Tred[(size_t)bo0 * TDIM + i];
    if (tid < BO_PER_BLK)
        biasS[tid] = conv_b[(bo0 + tid) & (OUTC - 1)];
    __syncthreads();

    #pragma unroll
    for (int jb = 0; jb < BO_PER_BLK; jb++) {
        const float bias = biasS[jb];
        float4* out4 = (float4*)(out + (size_t)(bo0 + jb) * 4096);
        const float* TsRow = &Ts[jb * TDIM];
        #pragma unroll
        for (int it = 0; it < 4; it++) {
            int q  = tid + it * 256;      // quad index; s' = 4*q
            int sp = q * 4;
            int p  = sp >> 11;
            int m  = (sp >> 5) & 63;
            int l0 = sp & 31;             // multiple of 4
            float tv = TsRow[p + m];
            float4 sw = *(const float4*)&swT[m * SWROW + l0];
            float4 r;
            r.x = fmaxf(fmaf(sw.x, tv, bias), 0.0f);
            r.y = fmaxf(fmaf(sw.y, tv, bias), 0.0f);
            r.z = fmaxf(fmaf(sw.z, tv, bias), 0.0f);
            r.w = fmaxf(fmaf(sw.w, tv, bias), 0.0f);
            out4[q] = r;
        }
    }
}

// ============================================================================
extern "C" void kernel_launch(void* const* d_in, const int* in_sizes, int n_in,
                              void* d_out, int out_size) {
    const float* x      = nullptr;
    const float* stft_w = nullptr;
    const float* conv_w = nullptr;
    const float* conv_b = nullptr;
    for (int i = 0; i < n_in; i++) {
        switch (in_sizes[i]) {
            case BQ * CCH * SLEN:  x      = (const float*)d_in[i]; break;  // 32768
            case NKF * KW:         stft_w = (const float*)d_in[i]; break;  // 2048
            case OUTC * 4096:      conv_w = (const float*)d_in[i]; break;  // 2097152
            case OUTC:             conv_b = (const float*)d_in[i]; break;  // 512
        }
    }

    gemm_partial_kernel<<<dim3(8, BQ, KSPLIT), 288>>>(x, conv_w);
    reduce_kernel<<<(BQ * OUTC * TDIM) / 256, 256>>>();
    epilogue_kernel<<<(BQ * OUTC) / BO_PER_BLK, 256>>>(stft_w, conv_b, (float*)d_out);
}